// round 15
// baseline (speedup 1.0000x reference)
#include <cuda_runtime.h>
#include <cuda_fp16.h>
#include <cstdint>

// Problem constants
#define BATCH   16384
#define MAXF    32
#define NFEAT   768
#define FT_OUT  1024
#define FULL_MASK 0xFFFFFFFFu
#define ROW_BYTES (FT_OUT * 2)     // 2048 B per fp16 row

// fp16 copy of ft_w, rebuilt every kernel_launch (deterministic).
__device__ __half g_ftw_h[NFEAT * FT_OUT];

// ---------------------------------------------------------------------------
// Kernel 1: ft_w fp32 -> fp16 (one float4 per thread)
// ---------------------------------------------------------------------------
__global__ void convert_ftw_kernel(const float* __restrict__ ftw) {
    int i = blockIdx.x * blockDim.x + threadIdx.x;
    float4 v = reinterpret_cast<const float4*>(ftw)[i];
    __half2* dst = reinterpret_cast<__half2*>(g_ftw_h);
    dst[2 * i + 0] = __floats2half2_rn(v.x, v.y);
    dst[2 * i + 1] = __floats2half2_rn(v.z, v.w);
}

// ---------------------------------------------------------------------------
// Kernel 2: ONE sample per CTA, 8 warps each owning 128 columns.
// Staging warp pre-computes BYTE OFFSETS (idx*2048) and pre-converted half2
// values once; worker warps consume them with 1 LDS.128 + 1 LDS.64 per
// 2 features — no extraction/multiply/convert ALU in the hot loop.
// Per feature per warp: 2x LDG.64 (256 B contiguous) + 4 HFMA2.
// ---------------------------------------------------------------------------
__global__ void __launch_bounds__(256, 6)
nnue_main_kernel(const float* __restrict__ values,
                 const int*   __restrict__ stm_idx,
                 const int*   __restrict__ nstm_idx,
                 const float* __restrict__ ft_b,
                 const float* __restrict__ out_w,
                 const float* __restrict__ out_b,
                 float*       __restrict__ out)
{
    __shared__ uint2   s_off[MAXF];    // {offS_bytes, offN_bytes} per feature
    __shared__ __half2 s_vh [MAXF];    // half2(value) per feature
    __shared__ float   s_partial[8];

    const int tid  = threadIdx.x;
    const int w    = tid >> 5;
    const int lane = tid & 31;
    const int b    = blockIdx.x;     // one sample per CTA

    // Stage metadata: warp 0, one feature per lane
    if (tid < 32) {
        const unsigned is = (unsigned)stm_idx [b * MAXF + tid];
        const unsigned in = (unsigned)nstm_idx[b * MAXF + tid];
        const float    v  = values [b * MAXF + tid];
        s_off[tid] = make_uint2(is * ROW_BYTES, in * ROW_BYTES);
        s_vh [tid] = __float2half2_rn(v);
    }
    __syncthreads();

    // Warp w owns cols [w*128, w*128+128): byte offset w*256; lane's 8 B chunk.
    const char* W = reinterpret_cast<const char*>(g_ftw_h) + w * 256 + lane * 8;
    const uint4* off4 = reinterpret_cast<const uint4*>(s_off);   // 2 feats/read
    const uint2* vh2  = reinterpret_cast<const uint2*>(s_vh);    // 2 feats/read

    __half2 aS0 = __half2half2(__float2half_rn(0.0f));
    __half2 aS1 = aS0, aN0 = aS0, aN1 = aS0;

    #pragma unroll
    for (int c = 0; c < 16; ++c) {            // 2 features per iteration
        const uint4 o = off4[c];              // {offS0, offN0, offS1, offN1}
        uint2 vv = vh2[c];                    // {vh0 bits, vh1 bits}
        const __half2 v0 = *reinterpret_cast<__half2*>(&vv.x);
        const __half2 v1 = *reinterpret_cast<__half2*>(&vv.y);

        // 4 independent LDG.64 (64-bit base + 32-bit precomputed offset)
        uint2 dS0 = *reinterpret_cast<const uint2*>(W + o.x);
        uint2 dN0 = *reinterpret_cast<const uint2*>(W + o.y);
        uint2 dS1 = *reinterpret_cast<const uint2*>(W + o.z);
        uint2 dN1 = *reinterpret_cast<const uint2*>(W + o.w);

        aS0 = __hfma2(v0, *reinterpret_cast<__half2*>(&dS0.x), aS0);
        aS1 = __hfma2(v0, *reinterpret_cast<__half2*>(&dS0.y), aS1);
        aN0 = __hfma2(v0, *reinterpret_cast<__half2*>(&dN0.x), aN0);
        aN1 = __hfma2(v0, *reinterpret_cast<__half2*>(&dN0.y), aN1);
        aS0 = __hfma2(v1, *reinterpret_cast<__half2*>(&dS1.x), aS0);
        aS1 = __hfma2(v1, *reinterpret_cast<__half2*>(&dS1.y), aS1);
        aN0 = __hfma2(v1, *reinterpret_cast<__half2*>(&dN1.x), aN0);
        aN1 = __hfma2(v1, *reinterpret_cast<__half2*>(&dN1.y), aN1);
    }

    // ----- epilogue: fp32 bias add, clip [0,1], dot with out_w -----
    // Lane owns cols w*128 + lane*4 .. +3 (both sides) -> float4 index w*32+lane
    const float4* fb4 = reinterpret_cast<const float4*>(ft_b);
    const float4* ow4 = reinterpret_cast<const float4*>(out_w);
    const int fidx = w * 32 + lane;

    float4 bb = fb4[fidx];
    float4 wS = ow4[fidx];
    float4 wN = ow4[256 + fidx];     // +256 float4 = +1024 cols (nstm half)

    float2 p0 = __half22float2(aS0), p1 = __half22float2(aS1);
    float2 r0 = __half22float2(aN0), r1 = __half22float2(aN1);

    float partial = 0.0f, hh;
    hh = fminf(fmaxf(p0.x + bb.x, 0.f), 1.f); partial = fmaf(hh, wS.x, partial);
    hh = fminf(fmaxf(p0.y + bb.y, 0.f), 1.f); partial = fmaf(hh, wS.y, partial);
    hh = fminf(fmaxf(p1.x + bb.z, 0.f), 1.f); partial = fmaf(hh, wS.z, partial);
    hh = fminf(fmaxf(p1.y + bb.w, 0.f), 1.f); partial = fmaf(hh, wS.w, partial);
    hh = fminf(fmaxf(r0.x + bb.x, 0.f), 1.f); partial = fmaf(hh, wN.x, partial);
    hh = fminf(fmaxf(r0.y + bb.y, 0.f), 1.f); partial = fmaf(hh, wN.y, partial);
    hh = fminf(fmaxf(r1.x + bb.z, 0.f), 1.f); partial = fmaf(hh, wN.z, partial);
    hh = fminf(fmaxf(r1.y + bb.w, 0.f), 1.f); partial = fmaf(hh, wN.w, partial);

    // warp reduce
    #pragma unroll
    for (int off = 16; off > 0; off >>= 1)
        partial += __shfl_xor_sync(FULL_MASK, partial, off);

    if (lane == 0) s_partial[w] = partial;
    __syncthreads();

    // warp 0 combines the 8 warp partials and finalizes
    if (tid < 32) {
        float p = (lane < 8) ? s_partial[lane] : 0.0f;
        #pragma unroll
        for (int off = 4; off > 0; off >>= 1)
            p += __shfl_xor_sync(FULL_MASK, p, off);
        if (lane == 0) {
            float x = p + out_b[0];
            out[b] = 1.0f / (1.0f + __expf(-x));
        }
    }
}

// ---------------------------------------------------------------------------
// kernel_launch
// Inputs: values, stm_indices, nstm_indices, ft_w, ft_b, out_w, out_b
// ---------------------------------------------------------------------------
extern "C" void kernel_launch(void* const* d_in, const int* in_sizes, int n_in,
                              void* d_out, int out_size)
{
    const float* values   = (const float*)d_in[0];
    const int*   stm_idx  = (const int*)  d_in[1];
    const int*   nstm_idx = (const int*)  d_in[2];
    const float* ft_w     = (const float*)d_in[3];
    const float* ft_b     = (const float*)d_in[4];
    const float* out_w    = (const float*)d_in[5];
    const float* out_b    = (const float*)d_in[6];
    float*       out      = (float*)d_out;

    convert_ftw_kernel<<<(NFEAT * FT_OUT / 4) / 256, 256>>>(ft_w);
    // one sample per CTA
    nnue_main_kernel<<<BATCH, 256>>>(values, stm_idx, nstm_idx,
                                     ft_b, out_w, out_b, out);
}

// round 16
// speedup vs baseline: 1.0731x; 1.0731x over previous
#include <cuda_runtime.h>
#include <cuda_fp16.h>
#include <cstdint>

// Problem constants
#define BATCH   16384
#define MAXF    32
#define NFEAT   768
#define FT_OUT  1024
#define FULL_MASK 0xFFFFFFFFu
#define ROW_BYTES (FT_OUT * 2)     // 2048 B per fp16 row

// fp16 copies, rebuilt every kernel_launch (deterministic).
__device__ __half g_ftw_h[NFEAT * FT_OUT];   // table
__device__ __half g_ftb_h[FT_OUT];           // bias
__device__ __half g_ow_h [2 * FT_OUT];       // output weights

// ---------------------------------------------------------------------------
// Kernel 1: convert table + bias + out_w fp32 -> fp16
// Blocks 0..767: table (one float4 per thread). Block 768: ftb + ow.
// ---------------------------------------------------------------------------
__global__ void convert_kernel(const float* __restrict__ ftw,
                               const float* __restrict__ ftb,
                               const float* __restrict__ ow) {
    const int bid = blockIdx.x;
    if (bid < 768) {
        int i = bid * 256 + threadIdx.x;
        float4 v = reinterpret_cast<const float4*>(ftw)[i];
        __half2* dst = reinterpret_cast<__half2*>(g_ftw_h);
        dst[2 * i + 0] = __floats2half2_rn(v.x, v.y);
        dst[2 * i + 1] = __floats2half2_rn(v.z, v.w);
    } else {
        const int t = threadIdx.x;
        for (int j = t; j < FT_OUT / 2; j += 256) {
            float2 x = reinterpret_cast<const float2*>(ftb)[j];
            reinterpret_cast<__half2*>(g_ftb_h)[j] = __floats2half2_rn(x.x, x.y);
        }
        for (int j = t; j < FT_OUT; j += 256) {
            float2 x = reinterpret_cast<const float2*>(ow)[j];
            reinterpret_cast<__half2*>(g_ow_h)[j] = __floats2half2_rn(x.x, x.y);
        }
    }
}

// ---------------------------------------------------------------------------
// Kernel 2: TWO warps per sample (512 cols each), 4 samples per CTA (R9 base).
// Staging precomputes byte offsets + half2 values. Inner iteration: 2 features,
// all 8 LDG.128 issued before FMAs (MLP=8). Epilogue uses fp16 ftb/ow
// (one uint4 = 8 halves per lane read) to halve epilogue wavefronts.
// ---------------------------------------------------------------------------
__global__ void __launch_bounds__(256, 4)
nnue_main_kernel(const float* __restrict__ values,
                 const int*   __restrict__ stm_idx,
                 const int*   __restrict__ nstm_idx,
                 const float* __restrict__ out_b,
                 float*       __restrict__ out)
{
    __shared__ uint2    s_off[4][MAXF];   // {offS_bytes, offN_bytes}
    __shared__ unsigned s_vh [4][MAXF];   // half2(value) bits
    __shared__ float    s_partial[8];

    const int tid       = threadIdx.x;
    const int warpInCta = tid >> 5;
    const int lane      = tid & 31;
    const int sInCta    = warpInCta >> 1;     // 4 samples per CTA
    const int h         = warpInCta & 1;      // column half: 0 or 1
    const int b         = blockIdx.x * 4 + sInCta;

    // Stage metadata: threads 0..127, one (sample, feature) each
    if (tid < 128) {
        const int s = tid >> 5;
        const int f = tid & 31;
        const int bg = blockIdx.x * 4 + s;
        const unsigned is = (unsigned)stm_idx [bg * MAXF + f];
        const unsigned in = (unsigned)nstm_idx[bg * MAXF + f];
        const float    v  = values [bg * MAXF + f];
        s_off[s][f] = make_uint2(is * ROW_BYTES, in * ROW_BYTES);
        __half2 vh = __float2half2_rn(v);
        s_vh[s][f] = *reinterpret_cast<unsigned*>(&vh);
    }
    __syncthreads();

    // Warp owns cols [h*512, h*512+512). Lane chunks: +lane*16 B and +512 B.
    const char* Wq = reinterpret_cast<const char*>(g_ftw_h) + h * 1024 + lane * 16;
    const uint4* off4 = reinterpret_cast<const uint4*>(s_off[sInCta]); // 2 feats
    const uint2* vh2  = reinterpret_cast<const uint2*>(s_vh[sInCta]);  // 2 feats

    __half2 accS[8], accN[8];
    #pragma unroll
    for (int i = 0; i < 8; ++i) {
        accS[i] = __half2half2(__float2half_rn(0.0f));
        accN[i] = accS[i];
    }

    #pragma unroll 4
    for (int c = 0; c < 16; ++c) {              // 2 features per iteration
        const uint4 o  = off4[c];               // {offS0, offN0, offS1, offN1}
        uint2 vv = vh2[c];
        const __half2 v0 = *reinterpret_cast<__half2*>(&vv.x);
        const __half2 v1 = *reinterpret_cast<__half2*>(&vv.y);

        const char* rS0 = Wq + o.x;
        const char* rN0 = Wq + o.y;
        const char* rS1 = Wq + o.z;
        const char* rN1 = Wq + o.w;

        // Issue all 8 independent LDG.128 first (MLP = 8)
        uint4 s0a = *reinterpret_cast<const uint4*>(rS0);
        uint4 s0b = *reinterpret_cast<const uint4*>(rS0 + 512);
        uint4 n0a = *reinterpret_cast<const uint4*>(rN0);
        uint4 n0b = *reinterpret_cast<const uint4*>(rN0 + 512);
        uint4 s1a = *reinterpret_cast<const uint4*>(rS1);
        uint4 s1b = *reinterpret_cast<const uint4*>(rS1 + 512);
        uint4 n1a = *reinterpret_cast<const uint4*>(rN1);
        uint4 n1b = *reinterpret_cast<const uint4*>(rN1 + 512);

        accS[0] = __hfma2(v0, *reinterpret_cast<__half2*>(&s0a.x), accS[0]);
        accS[1] = __hfma2(v0, *reinterpret_cast<__half2*>(&s0a.y), accS[1]);
        accS[2] = __hfma2(v0, *reinterpret_cast<__half2*>(&s0a.z), accS[2]);
        accS[3] = __hfma2(v0, *reinterpret_cast<__half2*>(&s0a.w), accS[3]);
        accS[4] = __hfma2(v0, *reinterpret_cast<__half2*>(&s0b.x), accS[4]);
        accS[5] = __hfma2(v0, *reinterpret_cast<__half2*>(&s0b.y), accS[5]);
        accS[6] = __hfma2(v0, *reinterpret_cast<__half2*>(&s0b.z), accS[6]);
        accS[7] = __hfma2(v0, *reinterpret_cast<__half2*>(&s0b.w), accS[7]);
        accN[0] = __hfma2(v0, *reinterpret_cast<__half2*>(&n0a.x), accN[0]);
        accN[1] = __hfma2(v0, *reinterpret_cast<__half2*>(&n0a.y), accN[1]);
        accN[2] = __hfma2(v0, *reinterpret_cast<__half2*>(&n0a.z), accN[2]);
        accN[3] = __hfma2(v0, *reinterpret_cast<__half2*>(&n0a.w), accN[3]);
        accN[4] = __hfma2(v0, *reinterpret_cast<__half2*>(&n0b.x), accN[4]);
        accN[5] = __hfma2(v0, *reinterpret_cast<__half2*>(&n0b.y), accN[5]);
        accN[6] = __hfma2(v0, *reinterpret_cast<__half2*>(&n0b.z), accN[6]);
        accN[7] = __hfma2(v0, *reinterpret_cast<__half2*>(&n0b.w), accN[7]);

        accS[0] = __hfma2(v1, *reinterpret_cast<__half2*>(&s1a.x), accS[0]);
        accS[1] = __hfma2(v1, *reinterpret_cast<__half2*>(&s1a.y), accS[1]);
        accS[2] = __hfma2(v1, *reinterpret_cast<__half2*>(&s1a.z), accS[2]);
        accS[3] = __hfma2(v1, *reinterpret_cast<__half2*>(&s1a.w), accS[3]);
        accS[4] = __hfma2(v1, *reinterpret_cast<__half2*>(&s1b.x), accS[4]);
        accS[5] = __hfma2(v1, *reinterpret_cast<__half2*>(&s1b.y), accS[5]);
        accS[6] = __hfma2(v1, *reinterpret_cast<__half2*>(&s1b.z), accS[6]);
        accS[7] = __hfma2(v1, *reinterpret_cast<__half2*>(&s1b.w), accS[7]);
        accN[0] = __hfma2(v1, *reinterpret_cast<__half2*>(&n1a.x), accN[0]);
        accN[1] = __hfma2(v1, *reinterpret_cast<__half2*>(&n1a.y), accN[1]);
        accN[2] = __hfma2(v1, *reinterpret_cast<__half2*>(&n1a.z), accN[2]);
        accN[3] = __hfma2(v1, *reinterpret_cast<__half2*>(&n1a.w), accN[3]);
        accN[4] = __hfma2(v1, *reinterpret_cast<__half2*>(&n1b.x), accN[4]);
        accN[5] = __hfma2(v1, *reinterpret_cast<__half2*>(&n1b.y), accN[5]);
        accN[6] = __hfma2(v1, *reinterpret_cast<__half2*>(&n1b.z), accN[6]);
        accN[7] = __hfma2(v1, *reinterpret_cast<__half2*>(&n1b.w), accN[7]);
    }

    // ----- epilogue: fp32 bias add, clip [0,1], dot with out_w (fp16 tables) -----
    // u in {0,1}: lane's 8 cols start at colbase = h*512 + u*256 + lane*8.
    float partial = 0.0f;
    #pragma unroll
    for (int u = 0; u < 2; ++u) {
        const int colbase = h * 512 + u * 256 + lane * 8;
        uint4 bbh = *reinterpret_cast<const uint4*>(g_ftb_h + colbase);
        float2 bb0 = __half22float2(*reinterpret_cast<__half2*>(&bbh.x));
        float2 bb1 = __half22float2(*reinterpret_cast<__half2*>(&bbh.y));
        float2 bb2 = __half22float2(*reinterpret_cast<__half2*>(&bbh.z));
        float2 bb3 = __half22float2(*reinterpret_cast<__half2*>(&bbh.w));

        #pragma unroll
        for (int side = 0; side < 2; ++side) {
            const __half2* acc = (side == 0) ? &accS[u*4] : &accN[u*4];
            uint4 wwh = *reinterpret_cast<const uint4*>(g_ow_h + side * FT_OUT + colbase);
            float2 w0 = __half22float2(*reinterpret_cast<__half2*>(&wwh.x));
            float2 w1 = __half22float2(*reinterpret_cast<__half2*>(&wwh.y));
            float2 w2 = __half22float2(*reinterpret_cast<__half2*>(&wwh.z));
            float2 w3 = __half22float2(*reinterpret_cast<__half2*>(&wwh.w));
            float2 p0 = __half22float2(acc[0]);
            float2 p1 = __half22float2(acc[1]);
            float2 p2 = __half22float2(acc[2]);
            float2 p3 = __half22float2(acc[3]);
            float hh;
            hh = fminf(fmaxf(p0.x + bb0.x, 0.f), 1.f); partial = fmaf(hh, w0.x, partial);
            hh = fminf(fmaxf(p0.y + bb0.y, 0.f), 1.f); partial = fmaf(hh, w0.y, partial);
            hh = fminf(fmaxf(p1.x + bb1.x, 0.f), 1.f); partial = fmaf(hh, w1.x, partial);
            hh = fminf(fmaxf(p1.y + bb1.y, 0.f), 1.f); partial = fmaf(hh, w1.y, partial);
            hh = fminf(fmaxf(p2.x + bb2.x, 0.f), 1.f); partial = fmaf(hh, w2.x, partial);
            hh = fminf(fmaxf(p2.y + bb2.y, 0.f), 1.f); partial = fmaf(hh, w2.y, partial);
            hh = fminf(fmaxf(p3.x + bb3.x, 0.f), 1.f); partial = fmaf(hh, w3.x, partial);
            hh = fminf(fmaxf(p3.y + bb3.y, 0.f), 1.f); partial = fmaf(hh, w3.y, partial);
        }
    }

    // warp reduce
    #pragma unroll
    for (int off = 16; off > 0; off >>= 1)
        partial += __shfl_xor_sync(FULL_MASK, partial, off);

    if (lane == 0) s_partial[warpInCta] = partial;
    __syncthreads();

    // half-0 warp of each sample finalizes
    if (h == 0 && lane == 0) {
        float x = s_partial[warpInCta] + s_partial[warpInCta + 1] + out_b[0];
        out[b] = 1.0f / (1.0f + __expf(-x));
    }
}

// ---------------------------------------------------------------------------
// kernel_launch
// Inputs: values, stm_indices, nstm_indices, ft_w, ft_b, out_w, out_b
// ---------------------------------------------------------------------------
extern "C" void kernel_launch(void* const* d_in, const int* in_sizes, int n_in,
                              void* d_out, int out_size)
{
    const float* values   = (const float*)d_in[0];
    const int*   stm_idx  = (const int*)  d_in[1];
    const int*   nstm_idx = (const int*)  d_in[2];
    const float* ft_w     = (const float*)d_in[3];
    const float* ft_b     = (const float*)d_in[4];
    const float* out_w    = (const float*)d_in[5];
    const float* out_b    = (const float*)d_in[6];
    float*       out      = (float*)d_out;

    convert_kernel<<<769, 256>>>(ft_w, ft_b, out_w);
    // 4 samples per CTA -> 4096 CTAs
    nnue_main_kernel<<<BATCH / 4, 256>>>(values, stm_idx, nstm_idx, out_b, out);
}